// round 1
// baseline (speedup 1.0000x reference)
#include <cuda_runtime.h>

// Problem constants (CustomLinear_20160576488054)
#define NTOK   32768          // B*N = 8*4096
#define EDIM   130            // 2*D + 2
#define DDIM   64
#define HHEADS 8
#define OUT_T  (NTOK * HHEADS * EDIM)   // elements per output tensor (q|k|v)

#define THREADS  256
#define TPB      128          // tokens per dense block
#define MS_PITCH 68           // 64 + 4 pad (keeps rows 16B aligned, shifts banks)
#define XS_PITCH 130          // 128 (duplicated 64) + 2 pad -> 130 % 32 != 0 banks ok
#define STOK     256          // tokens per sparse block

typedef unsigned long long u64;

__device__ __forceinline__ u64 ffma2(u64 a, u64 b, u64 c) {
    u64 d;
    asm("fma.rn.f32x2 %0, %1, %2, %3;" : "=l"(d) : "l"(a), "l"(b), "l"(c));
    return d;
}

// ---------------------------------------------------------------------------
// Dense kernel: 16 groups = q heads 0-3 (x2), k heads 0-3 (x1), v heads 0-7 (x1)
// Each block: 128 tokens x one head-row of E=130 floats (zeros + 64 dense + scalar)
// ---------------------------------------------------------------------------
extern "C" __global__ void __launch_bounds__(THREADS, 2)
dense_kernel(const float* __restrict__ x,
             const float* __restrict__ Mq,
             const float* __restrict__ Bq,
             const float* __restrict__ Mk,
             const float* __restrict__ Bk,
             const float* __restrict__ Mv,
             float* __restrict__ out)
{
    extern __shared__ float sm[];
    float* Ms = sm;                       // [64][MS_PITCH] transposed M
    float* Xs = sm + 64 * MS_PITCH;       // [TPB][XS_PITCH] duplicated x slice

    const int tile = blockIdx.x;
    const int g    = blockIdx.y;          // 0..15
    const int tid  = threadIdx.x;

    const float* M;
    int srcOff, tsel, h;
    float scal;
    bool hasScalar;
    if (g < 4)       { M = Mq + g * 4096;      srcOff = 65; tsel = 0; h = g;     scal = Bq[g]; hasScalar = true;  }
    else if (g < 8)  { int hh = g - 4;
                       M = Mk + hh * 4096;     srcOff = 0;  tsel = 1; h = hh;    scal = Bk[hh]; hasScalar = true; }
    else             { int hh = g - 8;
                       M = Mv + hh * 4096;     srcOff = 0;  tsel = 2; h = hh;    scal = 0.f;   hasScalar = false; }

    // Load M transposed: Ms[j][i] = M[i][j]  (out col i, contraction j)
    for (int idx = tid; idx < 4096; idx += THREADS) {
        int i = idx >> 6, j = idx & 63;
        Ms[j * MS_PITCH + i] = M[idx];
    }
    // Load x slice, duplicated for f32x2 broadcast
    const int tok0 = tile * TPB;
    for (int idx = tid; idx < TPB * 64; idx += THREADS) {
        int t = idx >> 6, j = idx & 63;
        float v = x[(tok0 + t) * EDIM + srcOff + j];
        Xs[t * XS_PITCH + 2 * j]     = v;
        Xs[t * XS_PITCH + 2 * j + 1] = v;
    }
    __syncthreads();

    const int tg = tid >> 3;   // 0..31 : token group -> tokens tg, tg+32, tg+64, tg+96
    const int cg = tid & 7;    // 0..7  : cols 8*cg .. 8*cg+7 (of 64 dense cols)

    u64 acc[4][4];
    #pragma unroll
    for (int a = 0; a < 4; a++)
        #pragma unroll
        for (int b = 0; b < 4; b++) acc[a][b] = 0ull;

    const float* msrow = Ms + cg * 8;
    const float* xrow0 = Xs + tg * XS_PITCH;

    #pragma unroll 8
    for (int kk = 0; kk < 64; kk++) {
        // b: 8 consecutive M cols as 4 f32x2 (two LDS.128)
        const u64* bp = reinterpret_cast<const u64*>(msrow + kk * MS_PITCH);
        u64 b0 = bp[0], b1 = bp[1], b2 = bp[2], b3 = bp[3];
        // a: duplicated scalars, one LDS.64 each, tokens strided by 32
        u64 a0 = *reinterpret_cast<const u64*>(xrow0 +  0 * XS_PITCH + 2 * kk);
        u64 a1 = *reinterpret_cast<const u64*>(xrow0 + 32 * XS_PITCH + 2 * kk);
        u64 a2 = *reinterpret_cast<const u64*>(xrow0 + 64 * XS_PITCH + 2 * kk);
        u64 a3 = *reinterpret_cast<const u64*>(xrow0 + 96 * XS_PITCH + 2 * kk);

        acc[0][0] = ffma2(a0, b0, acc[0][0]);
        acc[0][1] = ffma2(a0, b1, acc[0][1]);
        acc[0][2] = ffma2(a0, b2, acc[0][2]);
        acc[0][3] = ffma2(a0, b3, acc[0][3]);
        acc[1][0] = ffma2(a1, b0, acc[1][0]);
        acc[1][1] = ffma2(a1, b1, acc[1][1]);
        acc[1][2] = ffma2(a1, b2, acc[1][2]);
        acc[1][3] = ffma2(a1, b3, acc[1][3]);
        acc[2][0] = ffma2(a2, b0, acc[2][0]);
        acc[2][1] = ffma2(a2, b1, acc[2][1]);
        acc[2][2] = ffma2(a2, b2, acc[2][2]);
        acc[2][3] = ffma2(a2, b3, acc[2][3]);
        acc[3][0] = ffma2(a3, b0, acc[3][0]);
        acc[3][1] = ffma2(a3, b1, acc[3][1]);
        acc[3][2] = ffma2(a3, b2, acc[3][2]);
        acc[3][3] = ffma2(a3, b3, acc[3][3]);
    }

    // Dense epilogue: cols 65 + 8*cg + [0..7]
    const long obase = (long)tsel * OUT_T;
    #pragma unroll
    for (int j = 0; j < 4; j++) {
        long gt  = tok0 + tg + 32 * j;
        long row = obase + (gt * HHEADS + h) * EDIM;
        #pragma unroll
        for (int cp = 0; cp < 4; cp++) {
            const float* f = reinterpret_cast<const float*>(&acc[j][cp]);
            out[row + 65 + 8 * cg + 2 * cp]     = f[0];
            out[row + 65 + 8 * cg + 2 * cp + 1] = f[1];
        }
    }

    // Zeros: cols 0..64 of every token in this row
    for (int i = tid; i < TPB * 65; i += THREADS) {
        int t = i / 65, c = i - t * 65;
        long gt = tok0 + t;
        out[obase + (gt * HHEADS + h) * EDIM + c] = 0.f;
    }
    // Col 129: scalar (q/k dense heads) or zero (v)
    for (int t = tid; t < TPB; t += THREADS) {
        long gt = tok0 + t;
        float v = hasScalar ? x[gt * EDIM + 129] * scal : 0.f;
        out[obase + (gt * HHEADS + h) * EDIM + 129] = v;
    }
}

// ---------------------------------------------------------------------------
// Sparse kernel: 8 groups = q heads 4-7 (col65 = s_last*bq), k heads 4-7
// (col65 = s_mid*bk). Entire 130-float rows: zeros + one scalar.
// ---------------------------------------------------------------------------
extern "C" __global__ void __launch_bounds__(THREADS)
sparse_kernel(const float* __restrict__ x,
              const float* __restrict__ Bq,
              const float* __restrict__ Bk,
              float* __restrict__ out)
{
    __shared__ float sv[STOK];
    const int g    = blockIdx.y;   // 0..7
    const int tok0 = blockIdx.x * STOK;
    const int tid  = threadIdx.x;

    int tsel, h, sidx;
    float scale;
    if (g < 4) { tsel = 0; h = 4 + g; sidx = 129; scale = Bq[h]; }  // q: s_last
    else       { tsel = 1; h = g;     sidx = 64;  scale = Bk[h]; }  // k: s_mid

    sv[tid] = x[(tok0 + tid) * EDIM + sidx] * scale;
    __syncthreads();

    const long obase = (long)tsel * OUT_T;
    for (int i = tid; i < STOK * EDIM; i += THREADS) {
        int t = i / EDIM, c = i - t * EDIM;
        long gt = tok0 + t;
        out[obase + (gt * HHEADS + h) * EDIM + c] = (c == 65) ? sv[t] : 0.f;
    }
}

// ---------------------------------------------------------------------------
extern "C" void kernel_launch(void* const* d_in, const int* in_sizes, int n_in,
                              void* d_out, int out_size)
{
    const float* x  = (const float*)d_in[0];
    const float* Mq = (const float*)d_in[1];
    const float* Bq = (const float*)d_in[2];
    const float* Mk = (const float*)d_in[3];
    const float* Bk = (const float*)d_in[4];
    const float* Mv = (const float*)d_in[5];
    float* out = (float*)d_out;

    const int smemBytes = (64 * MS_PITCH + TPB * XS_PITCH) * (int)sizeof(float); // ~84 KB
    cudaFuncSetAttribute(dense_kernel, cudaFuncAttributeMaxDynamicSharedMemorySize, smemBytes);

    dense_kernel<<<dim3(NTOK / TPB, 16), THREADS, smemBytes>>>(x, Mq, Bq, Mk, Bk, Mv, out);
    sparse_kernel<<<dim3(NTOK / STOK, 8), THREADS>>>(x, Bq, Bk, out);
}

// round 2
// speedup vs baseline: 1.3026x; 1.3026x over previous
#include <cuda_runtime.h>

// ---------------------------------------------------------------------------
// CustomLinear_20160576488054  (B=8, N=4096, D=64, H=8, P=4, E=130)
// out = concat(q,k,v), each (32768, 8*130) fp32.
// Dense work: 16 GEMV-groups of 64x64 (q h0-3 from x2; k h0-3 from x1; v h0-7
// from x1). Everything else is zeros + 16 scalar columns.
// ---------------------------------------------------------------------------

#define NTOK   32768
#define EDIM   130
#define HHEADS 8
#define OUT_T  (NTOK * HHEADS * EDIM)      // 34,078,720 floats per tensor
#define THREADS 256
#define TPB     128                         // tokens per block
#define MS_PITCH 68                         // 64 + 4 pad floats per k-row of M

typedef unsigned long long u64;
typedef unsigned int u32;

__device__ __forceinline__ u64 ffma2(u64 a, u64 b, u64 c) {
    u64 d;
    asm("fma.rn.f32x2 %0, %1, %2, %3;" : "=l"(d) : "l"(a), "l"(b), "l"(c));
    return d;
}
__device__ __forceinline__ u64 pack2(float lo, float hi) {
    u64 d;
    asm("mov.b64 %0, {%1, %2};" : "=l"(d) : "f"(lo), "f"(hi));
    return d;
}
__device__ __forceinline__ void unpack2(u64 v, float& lo, float& hi) {
    asm("mov.b64 {%0, %1}, %2;" : "=f"(lo), "=f"(hi) : "l"(v));
}

// Column permutation for M in smem: i = 16*cg + 4*q + r  ->  16*q + 4*cg + r.
// Makes each LDS.128 (fixed q, 4 distinct cg) span one 64B region -> 1 wavefront.
__device__ __forceinline__ int permcol(int i) {
    return (((i >> 2) & 3) << 4) | ((i >> 4) << 2) | (i & 3);
}

extern "C" __global__ void __launch_bounds__(THREADS, 2)
fused_kernel(const float* __restrict__ x,
             const float* __restrict__ Mq,
             const float* __restrict__ Bq,
             const float* __restrict__ Mk,
             const float* __restrict__ Bk,
             const float* __restrict__ Mv,
             float* __restrict__ out)
{
    extern __shared__ float sm[];
    const int g    = blockIdx.x;          // 0..23 (group: fast dim -> token locality)
    const int tile = blockIdx.y;          // 0..255
    const int tid  = threadIdx.x;
    const int tok0 = tile * TPB;

    // ---------------- sparse head-rows: q h4-7, k h4-7 (zeros + 1 scalar) ----
    if (g >= 16) {
        const int gg = g - 16;            // 0..7
        int tsel, h, sidx; float scale;
        if (gg < 4) { tsel = 0; h = 4 + gg; sidx = 129; scale = Bq[h]; }  // q: s_last
        else        { tsel = 1; h = gg;     sidx = 64;  scale = Bk[h]; }  // k: s_mid

        float* sv = sm;                   // [TPB]
        if (tid < TPB)
            sv[tid] = x[(size_t)(tok0 + tid) * EDIM + sidx] * scale;
        __syncthreads();

        u64* O = reinterpret_cast<u64*>(out)
               + (size_t)tsel * (OUT_T / 2) + (size_t)h * 65 + (size_t)tok0 * 520;
        for (int i = tid; i < TPB * 65; i += THREADS) {
            int t = i / 65;               // div-by-const -> mul+shift
            int c = i - t * 65;
            u64 v = (c == 32) ? pack2(0.f, sv[t]) : 0ull;   // floats (64, 65)
            O[(size_t)t * 520 + c] = v;
        }
        return;
    }

    // ---------------- dense head-rows --------------------------------------
    const float* M;
    int srcOff, tsel, h; float scal; bool hasScalar;
    if (g < 4)      { M = Mq + g * 4096;        srcOff = 65; tsel = 0; h = g;     scal = Bq[g];     hasScalar = true;  }
    else if (g < 8) { int hh = g - 4;
                      M = Mk + hh * 4096;       srcOff = 0;  tsel = 1; h = hh;    scal = Bk[hh];    hasScalar = true;  }
    else            { int hh = g - 8;
                      M = Mv + hh * 4096;       srcOff = 0;  tsel = 2; h = hh;    scal = 0.f;       hasScalar = false; }

    float* Ms = sm;                        // [64 k][MS_PITCH] permuted-transposed M
    float* Xs = sm + 64 * MS_PITCH;        // [TPB][130] duplicated x slice; later staging

    // M transposed + column-permuted: Ms[j][perm(i)] = M[i][j]
    for (int idx = tid; idx < 4096; idx += THREADS) {
        int i = idx >> 6, j = idx & 63;
        Ms[j * MS_PITCH + permcol(i)] = M[idx];
    }
    // x slice duplicated: Xs[t][2j] = Xs[t][2j+1] = x[t][srcOff+j]
    for (int idx = tid; idx < TPB * 64; idx += THREADS) {
        int t = idx >> 6, j = idx & 63;
        float v = x[(size_t)(tok0 + t) * EDIM + srcOff + j];
        Xs[t * EDIM + 2 * j]     = v;
        Xs[t * EDIM + 2 * j + 1] = v;
    }
    __syncthreads();

    const int cg = tid & 3;                // 16 output cols: 16cg .. 16cg+15
    const int tg = tid >> 2;               // tokens tg and tg+64

    u64 acc[2][8];
    #pragma unroll
    for (int a = 0; a < 2; a++)
        #pragma unroll
        for (int m = 0; m < 8; m++) acc[a][m] = 0ull;

    const float4* Bp = reinterpret_cast<const float4*>(Ms) + cg;   // +cg*4 floats
    const u64*    X0 = reinterpret_cast<const u64*>(Xs + tg * EDIM);
    const u64*    X1 = reinterpret_cast<const u64*>(Xs + (tg + 64) * EDIM);

    #pragma unroll 4
    for (int kk = 0; kk < 64; kk++) {
        u64 A0 = X0[kk];                   // (x, x) duplicated pair
        u64 A1 = X1[kk];
        #pragma unroll
        for (int q = 0; q < 4; q++) {
            float4 f = Bp[kk * 17 + q * 4];            // Ms + kk*68 + q*16 + cg*4
            u64 b0 = pack2(f.x, f.y);                  // cols 16cg+4q+0,1
            u64 b1 = pack2(f.z, f.w);                  // cols 16cg+4q+2,3
            acc[0][2 * q]     = ffma2(A0, b0, acc[0][2 * q]);
            acc[0][2 * q + 1] = ffma2(A0, b1, acc[0][2 * q + 1]);
            acc[1][2 * q]     = ffma2(A1, b0, acc[1][2 * q]);
            acc[1][2 * q + 1] = ffma2(A1, b1, acc[1][2 * q + 1]);
        }
    }

    // ---------------- epilogue: stage full 130-float rows, stream out ------
    __syncthreads();                       // everyone done reading Xs

    u64* stg64 = reinterpret_cast<u64*>(Xs);   // staging aliases Xs: [TPB][65] u64
    for (int i = tid; i < TPB * 65; i += THREADS) stg64[i] = 0ull;
    __syncthreads();

    float* stg = Xs;
    #pragma unroll
    for (int jt = 0; jt < 2; jt++) {
        int t = tg + 64 * jt;
        int base = t * EDIM + 65 + 16 * cg;
        #pragma unroll
        for (int m = 0; m < 8; m++) {
            float lo, hi;
            unpack2(acc[jt][m], lo, hi);
            stg[base + 2 * m]     = lo;
            stg[base + 2 * m + 1] = hi;
        }
    }
    if (hasScalar && tid < TPB)
        stg[tid * EDIM + 129] = x[(size_t)(tok0 + tid) * EDIM + 129] * scal;
    __syncthreads();

    u64* O = reinterpret_cast<u64*>(out)
           + (size_t)tsel * (OUT_T / 2) + (size_t)h * 65 + (size_t)tok0 * 520;
    for (int i = tid; i < TPB * 65; i += THREADS) {
        int t = i / 65;
        int c = i - t * 65;
        O[(size_t)t * 520 + c] = stg64[i];
    }
}

// ---------------------------------------------------------------------------
extern "C" void kernel_launch(void* const* d_in, const int* in_sizes, int n_in,
                              void* d_out, int out_size)
{
    const float* x  = (const float*)d_in[0];
    const float* Mq = (const float*)d_in[1];
    const float* Bq = (const float*)d_in[2];
    const float* Mk = (const float*)d_in[3];
    const float* Bk = (const float*)d_in[4];
    const float* Mv = (const float*)d_in[5];
    float* out = (float*)d_out;

    const int smemBytes = (64 * MS_PITCH + TPB * EDIM) * (int)sizeof(float); // 83,968 B
    cudaFuncSetAttribute(fused_kernel, cudaFuncAttributeMaxDynamicSharedMemorySize, smemBytes);

    fused_kernel<<<dim3(24, NTOK / TPB), THREADS, smemBytes>>>(x, Mq, Bq, Mk, Bk, Mv, out);
}